// round 12
// baseline (speedup 1.0000x reference)
#include <cuda_runtime.h>
#include <cuda_bf16.h>
#include <cstdint>

#define B_ROWS     524288
#define D_DIM      64
#define TILE       256
#define THREADS    256
#define GRID       148               // 1 block per SM
#define NTILES     (B_ROWS / TILE)   // 2048
#define NSTAGE     3
#define HALF_ROWS  128
#define PAD_STRIDE 68                              // floats; LDGSTS half
#define PAD_FLOATS (HALF_ROWS * PAD_STRIDE)        // 8704
#define CON_FLOATS (HALF_ROWS * D_DIM)             // 8192 (TMA half, contiguous)
#define STG_FLOATS (PAD_FLOATS + CON_FLOATS)       // 16896 -> 67584 B, 128B-aligned
#define HALF_BYTES (HALF_ROWS * D_DIM * 4)         // 32768
#define SMEM_BYTES (NSTAGE * STG_FLOATS * 4 + 9000 * 2)   // 220752 B

__device__ float        g_part[GRID];
__device__ unsigned int g_count = 0;   // reset by last block every call

__device__ __forceinline__ void cp_async16(uint32_t saddr, const void* gptr) {
    asm volatile("cp.async.cg.shared.global [%0], [%1], 16;\n"
                 :: "r"(saddr), "l"(gptr) : "memory");
}

__device__ __forceinline__ void mbar_wait(uint32_t mbar, uint32_t parity) {
    uint32_t done;
    asm volatile(
        "{\n\t.reg .pred p;\n\t"
        "mbarrier.try_wait.parity.acquire.cta.shared::cta.b64 p, [%1], %2;\n\t"
        "selp.b32 %0, 1, 0, p;\n\t}"
        : "=r"(done) : "r"(mbar), "r"(parity) : "memory");
    if (!done) {
        asm volatile(
            "{\n\t.reg .pred P1;\n\t"
            "WL_%=:\n\t"
            "mbarrier.try_wait.parity.acquire.cta.shared::cta.b64 P1, [%0], %1, 0x989680;\n\t"
            "@P1 bra.uni WD_%=;\n\t"
            "bra.uni WL_%=;\n\t"
            "WD_%=:\n\t}"
            :: "r"(mbar), "r"(parity) : "memory");
    }
}

__device__ __forceinline__ void bulk_copy(uint32_t dst_smem, const void* src,
                                          uint32_t bytes, uint32_t mbar) {
    asm volatile("mbarrier.arrive.expect_tx.shared.b64 _, [%0], %1;"
                 :: "r"(mbar), "r"(bytes) : "memory");
    asm volatile(
        "cp.async.bulk.shared::cluster.global.mbarrier::complete_tx::bytes "
        "[%0], [%1], %2, [%3];"
        :: "r"(dst_smem), "l"(src), "r"(bytes), "r"(mbar) : "memory");
}

// stage one tile: rows 0-127 via LDGSTS (padded), rows 128-255 via TMA (contig)
__device__ __forceinline__ void stage_tile(float* stg_base, uint32_t stg_u32,
                                           const float* gtile, uint32_t mbar,
                                           int tid)
{
    // LDGSTS half: 2048 quads, 8 per thread, coalesced
    const float4* gq = (const float4*)gtile;
    #pragma unroll
    for (int k = 0; k < 8; k++) {
        int f   = k * THREADS + tid;
        int row = f >> 4;
        int c4  = f & 15;
        uint32_t saddr = (uint32_t)__cvta_generic_to_shared(
            stg_base + row * PAD_STRIDE + c4 * 4);
        cp_async16(saddr, gq + f);
    }
    asm volatile("cp.async.commit_group;\n" ::: "memory");

    // TMA half
    if (tid == 0)
        bulk_copy(stg_u32 + PAD_FLOATS * 4,
                  gtile + HALF_ROWS * D_DIM, HALF_BYTES, mbar);
}

__global__ void __launch_bounds__(THREADS, 1) mcl_main(
    const float* __restrict__ x,
    const int*   __restrict__ labels,   // int32 on device
    const float* __restrict__ lin_w,
    const float* __restrict__ lin_b,
    const float* __restrict__ linear_p,
    const float* __restrict__ bias_p,
    const float* __restrict__ centers,
    float*       __restrict__ out)
{
    extern __shared__ __align__(128) float smem[];
    float*         sx   = smem;                                 // NSTAGE stages
    __nv_bfloat16* stab = (__nv_bfloat16*)(smem + NSTAGE * STG_FLOATS);
    __shared__ __align__(16) float sw[D_DIM];
    __shared__ __align__(8) unsigned long long mbar[NSTAGE];
    __shared__ float warp_acc[THREADS / 32];
    __shared__ bool  s_last;

    const int tid = threadIdx.x;
    const int bid = blockIdx.x;
    const uint32_t smem_u32 = (uint32_t)__cvta_generic_to_shared(smem);
    const uint32_t mbar_u32 = (uint32_t)__cvta_generic_to_shared(mbar);

    if (tid == 0) {
        #pragma unroll
        for (int i = 0; i < NSTAGE; i++)
            asm volatile("mbarrier.init.shared.b64 [%0], 1;"
                         :: "r"(mbar_u32 + 8 * i) : "memory");
    }
    __syncthreads();

    // prologue: stage tiles bid and bid+GRID (both always exist: 295 < 2048)
    stage_tile(sx,              smem_u32,
               x + (size_t)bid * TILE * D_DIM, mbar_u32, tid);
    stage_tile(sx + STG_FLOATS, smem_u32 + STG_FLOATS * 4,
               x + (size_t)(bid + GRID) * TILE * D_DIM, mbar_u32 + 8, tid);

    // tables -> bf16 in shared (overlapped with fills)
    for (int i = tid; i < 3000; i += THREADS) {
        stab[i]        = __float2bfloat16(__ldg(linear_p + i));
        stab[3000 + i] = __float2bfloat16(__ldg(bias_p   + i));
        stab[6000 + i] = __float2bfloat16(__ldg(centers  + i));
    }
    if (tid < D_DIM / 4)
        ((float4*)sw)[tid] = ((const float4*)lin_w)[tid];
    const float lb = __ldg(lin_b);

    float acc = 0.f;
    int it = 0;

    for (int tile = bid; tile < NTILES; tile += GRID, ++it) {
        const int s = it % NSTAGE;
        const int nxt2 = tile + 2 * GRID;
        if (nxt2 < NTILES) {
            const int s2 = (it + 2) % NSTAGE;
            stage_tile(sx + s2 * STG_FLOATS, smem_u32 + s2 * STG_FLOATS * 4,
                       x + (size_t)nxt2 * TILE * D_DIM, mbar_u32 + 8 * s2, tid);
        }

        int lab = __ldg(&labels[tile * TILE + tid]);
        lab = min(max(lab, 0), 999);

        // wait LDGSTS half (commit from 2 iterations ago)
        if (nxt2 < NTILES)
            asm volatile("cp.async.wait_group 2;\n" ::: "memory");
        else if (tile + GRID < NTILES)
            asm volatile("cp.async.wait_group 1;\n" ::: "memory");
        else
            asm volatile("cp.async.wait_group 0;\n" ::: "memory");
        // wait TMA half
        mbar_wait(mbar_u32 + 8 * s, (uint32_t)((it / NSTAGE) & 1));
        __syncthreads();

        // one thread per row; warps 0-3 padded half, warps 4-7 contiguous half
        const float* stg = sx + s * STG_FLOATS;
        const float4* swq = (const float4*)sw;
        float m = 0.f, ssum = 0.f, q = 0.f;
        if (tid < HALF_ROWS) {
            const float4* xr = (const float4*)(stg + tid * PAD_STRIDE);
            #pragma unroll
            for (int j = 0; j < 16; j++) {
                float4 v = xr[j];
                float4 w = swq[j];
                m = fmaf(v.x, w.x, m); m = fmaf(v.y, w.y, m);
                m = fmaf(v.z, w.z, m); m = fmaf(v.w, w.w, m);
                ssum += (v.x + v.y) + (v.z + v.w);
                q = fmaf(v.x, v.x, q); q = fmaf(v.y, v.y, q);
                q = fmaf(v.z, v.z, q); q = fmaf(v.w, v.w, q);
            }
        } else {
            const int rr = tid - HALF_ROWS;
            const float4* xr = (const float4*)(stg + PAD_FLOATS) + rr * 16;
            #pragma unroll
            for (int j = 0; j < 16; j++) {
                const int qi = (j + rr) & 15;   // rotation: conflict-free phases
                float4 v = xr[qi];
                float4 w = swq[qi];
                m = fmaf(v.x, w.x, m); m = fmaf(v.y, w.y, m);
                m = fmaf(v.z, w.z, m); m = fmaf(v.w, w.w, m);
                ssum += (v.x + v.y) + (v.z + v.w);
                q = fmaf(v.x, v.x, q); q = fmaf(v.y, v.y, q);
                q = fmaf(v.z, v.z, q); q = fmaf(v.w, v.w, q);
            }
        }
        m += lb;

        const int l3 = lab * 3;
        const float A0 = __bfloat162float(stab[l3 + 0]);
        const float A1 = __bfloat162float(stab[l3 + 1]);
        const float A2 = __bfloat162float(stab[l3 + 2]);
        const float B0 = __bfloat162float(stab[3000 + l3 + 0]);
        const float B1 = __bfloat162float(stab[3000 + l3 + 1]);
        const float B2 = __bfloat162float(stab[3000 + l3 + 2]);
        const float C0 = __bfloat162float(stab[6000 + l3 + 0]);
        const float C1 = __bfloat162float(stab[6000 + l3 + 1]);
        const float C2 = __bfloat162float(stab[6000 + l3 + 2]);

        const float l0 = fmaf(m, A0, B0);
        const float l1 = fmaf(m, A1, B1);
        const float l2 = fmaf(m, A2, B2);
        const float mx = fmaxf(l0, fmaxf(l1, l2));
        const float e0 = __expf(l0 - mx);
        const float e1 = __expf(l1 - mx);
        const float e2 = __expf(l2 - mx);
        const float inv = 1.f / (e0 + e1 + e2);

        const float t0 = C0 * fmaf(64.f, C0, -2.f * ssum);
        const float t1 = C1 * fmaf(64.f, C1, -2.f * ssum);
        const float t2 = C2 * fmaf(64.f, C2, -2.f * ssum);
        acc += q + inv * (e0 * t0 + e1 * t1 + e2 * t2);

        __syncthreads();   // all reads of stage s done before it is restaged
    }

    // block reduction
    #pragma unroll
    for (int o = 16; o > 0; o >>= 1)
        acc += __shfl_xor_sync(0xffffffffu, acc, o);
    if ((tid & 31) == 0)
        warp_acc[tid >> 5] = acc;
    __syncthreads();
    if (tid == 0) {
        float t = 0.f;
        #pragma unroll
        for (int i = 0; i < THREADS / 32; i++) t += warp_acc[i];
        g_part[bid] = t;
        __threadfence();
        unsigned int old = atomicAdd(&g_count, 1u);
        s_last = (old == GRID - 1);
    }
    __syncthreads();

    // last block finalizes: fixed-order double reduction (deterministic)
    if (s_last && tid < 32) {
        double t = 0.0;
        for (int i = tid; i < GRID; i += 32)
            t += (double)g_part[i];
        #pragma unroll
        for (int o = 16; o > 0; o >>= 1)
            t += __shfl_xor_sync(0xffffffffu, t, o);
        if (tid == 0) {
            out[0] = (float)(t / (double)B_ROWS);
            g_count = 0;   // rearm for next graph replay
        }
    }
}

extern "C" void kernel_launch(void* const* d_in, const int* in_sizes, int n_in,
                              void* d_out, int out_size)
{
    const float* x        = (const float*)d_in[0];
    const int*   labels   = (const int*)d_in[1];
    const float* lin_w    = (const float*)d_in[2];
    const float* lin_b    = (const float*)d_in[3];
    const float* linear_p = (const float*)d_in[4];
    const float* bias_p   = (const float*)d_in[5];
    const float* centers  = (const float*)d_in[6];

    cudaFuncSetAttribute(mcl_main,
                         cudaFuncAttributeMaxDynamicSharedMemorySize, SMEM_BYTES);
    mcl_main<<<GRID, THREADS, SMEM_BYTES>>>(x, labels, lin_w, lin_b,
                                            linear_p, bias_p, centers,
                                            (float*)d_out);
}

// round 13
// speedup vs baseline: 1.0197x; 1.0197x over previous
#include <cuda_runtime.h>
#include <cstdint>

#define B_ROWS   524288
#define D_DIM    64
#define THREADS  512
#define GRID     296                       // 148 SMs * 2 CTAs
#define RPP      (GRID * THREADS / 4)      // rows per pass = 37888

__device__ float        g_part[GRID];
__device__ unsigned int g_count = 0;       // reset by last block every call

__device__ __forceinline__ float row_epilogue(
    float m, float s, float q, int lab, float lb, const float* __restrict__ stab)
{
    m += lb;
    const int l3 = lab * 3;
    const float A0 = stab[l3 + 0];
    const float A1 = stab[l3 + 1];
    const float A2 = stab[l3 + 2];
    const float B0 = stab[3000 + l3 + 0];
    const float B1 = stab[3000 + l3 + 1];
    const float B2 = stab[3000 + l3 + 2];
    const float C0 = stab[6000 + l3 + 0];
    const float C1 = stab[6000 + l3 + 1];
    const float C2 = stab[6000 + l3 + 2];

    const float l0 = fmaf(m, A0, B0);
    const float l1 = fmaf(m, A1, B1);
    const float l2 = fmaf(m, A2, B2);
    const float mx = fmaxf(l0, fmaxf(l1, l2));
    const float e0 = __expf(l0 - mx);
    const float e1 = __expf(l1 - mx);
    const float e2 = __expf(l2 - mx);
    const float inv = 1.f / (e0 + e1 + e2);

    const float t0 = C0 * fmaf(64.f, C0, -2.f * s);
    const float t1 = C1 * fmaf(64.f, C1, -2.f * s);
    const float t2 = C2 * fmaf(64.f, C2, -2.f * s);
    return q + inv * (e0 * t0 + e1 * t1 + e2 * t2);
}

__global__ void __launch_bounds__(THREADS, 2) mcl_main(
    const float* __restrict__ x,
    const int*   __restrict__ labels,   // int32 on device
    const float* __restrict__ lin_w,
    const float* __restrict__ lin_b,
    const float* __restrict__ linear_p,
    const float* __restrict__ bias_p,
    const float* __restrict__ centers,
    float*       __restrict__ out)
{
    __shared__ __align__(16) float stab[9000];   // fp32 tables: A | B | C
    __shared__ __align__(16) float sw[D_DIM];
    __shared__ float warp_acc[THREADS / 32];
    __shared__ bool  s_last;

    const int tid  = threadIdx.x;
    const int bid  = blockIdx.x;
    const int gtid = bid * THREADS + tid;
    const int qq   = tid & 3;            // quarter of the row this thread owns
    const int rb   = gtid >> 2;          // base row

    // fill tables + weights (coalesced), one-time
    for (int i = tid; i < 3000; i += THREADS) {
        stab[i]        = __ldg(linear_p + i);
        stab[3000 + i] = __ldg(bias_p   + i);
        stab[6000 + i] = __ldg(centers  + i);
    }
    if (tid < D_DIM / 4)
        ((float4*)sw)[tid] = ((const float4*)lin_w)[tid];
    const float lb = __ldg(lin_b);
    __syncthreads();

    const float4* swq = (const float4*)sw;
    float acc = 0.f;

    for (int r0 = rb; r0 < B_ROWS; r0 += 2 * RPP) {
        const int  r1 = r0 + RPP;
        const bool h2 = r1 < B_ROWS;     // uniform across warp

        // front-batch 8 LDG.128 (fully coalesced: warp = 8 rows x 256B contiguous)
        const float4* p0 = (const float4*)(x + (size_t)r0 * D_DIM) + qq * 4;
        float4 v0a = __ldg(p0 + 0), v0b = __ldg(p0 + 1);
        float4 v0c = __ldg(p0 + 2), v0d = __ldg(p0 + 3);
        float4 v1a, v1b, v1c, v1d;
        if (h2) {
            const float4* p1 = (const float4*)(x + (size_t)r1 * D_DIM) + qq * 4;
            v1a = __ldg(p1 + 0); v1b = __ldg(p1 + 1);
            v1c = __ldg(p1 + 2); v1d = __ldg(p1 + 3);
        }
        int lab0 = 0, lab1 = 0;
        if (qq == 0) {
            lab0 = min(max(__ldg(labels + r0), 0), 999);
            if (h2) lab1 = min(max(__ldg(labels + r1), 0), 999);
        }

        const float4 w0 = swq[qq * 4 + 0];
        const float4 w1 = swq[qq * 4 + 1];
        const float4 w2 = swq[qq * 4 + 2];
        const float4 w3 = swq[qq * 4 + 3];

        // ---- row 0 partials over this thread's 4 quads
        {
            float m = v0a.x * w0.x;           m = fmaf(v0a.y, w0.y, m);
            m = fmaf(v0a.z, w0.z, m);         m = fmaf(v0a.w, w0.w, m);
            m = fmaf(v0b.x, w1.x, m);         m = fmaf(v0b.y, w1.y, m);
            m = fmaf(v0b.z, w1.z, m);         m = fmaf(v0b.w, w1.w, m);
            m = fmaf(v0c.x, w2.x, m);         m = fmaf(v0c.y, w2.y, m);
            m = fmaf(v0c.z, w2.z, m);         m = fmaf(v0c.w, w2.w, m);
            m = fmaf(v0d.x, w3.x, m);         m = fmaf(v0d.y, w3.y, m);
            m = fmaf(v0d.z, w3.z, m);         m = fmaf(v0d.w, w3.w, m);

            float s = (v0a.x + v0a.y) + (v0a.z + v0a.w);
            s += (v0b.x + v0b.y) + (v0b.z + v0b.w);
            s += (v0c.x + v0c.y) + (v0c.z + v0c.w);
            s += (v0d.x + v0d.y) + (v0d.z + v0d.w);

            float q = v0a.x * v0a.x;          q = fmaf(v0a.y, v0a.y, q);
            q = fmaf(v0a.z, v0a.z, q);        q = fmaf(v0a.w, v0a.w, q);
            q = fmaf(v0b.x, v0b.x, q);        q = fmaf(v0b.y, v0b.y, q);
            q = fmaf(v0b.z, v0b.z, q);        q = fmaf(v0b.w, v0b.w, q);
            q = fmaf(v0c.x, v0c.x, q);        q = fmaf(v0c.y, v0c.y, q);
            q = fmaf(v0c.z, v0c.z, q);        q = fmaf(v0c.w, v0c.w, q);
            q = fmaf(v0d.x, v0d.x, q);        q = fmaf(v0d.y, v0d.y, q);
            q = fmaf(v0d.z, v0d.z, q);        q = fmaf(v0d.w, v0d.w, q);

            // 4-lane butterfly (2 steps)
            m += __shfl_xor_sync(0xffffffffu, m, 1);
            s += __shfl_xor_sync(0xffffffffu, s, 1);
            q += __shfl_xor_sync(0xffffffffu, q, 1);
            m += __shfl_xor_sync(0xffffffffu, m, 2);
            s += __shfl_xor_sync(0xffffffffu, s, 2);
            q += __shfl_xor_sync(0xffffffffu, q, 2);

            if (qq == 0)
                acc += row_epilogue(m, s, q, lab0, lb, stab);
        }

        // ---- row 1
        if (h2) {
            float m = v1a.x * w0.x;           m = fmaf(v1a.y, w0.y, m);
            m = fmaf(v1a.z, w0.z, m);         m = fmaf(v1a.w, w0.w, m);
            m = fmaf(v1b.x, w1.x, m);         m = fmaf(v1b.y, w1.y, m);
            m = fmaf(v1b.z, w1.z, m);         m = fmaf(v1b.w, w1.w, m);
            m = fmaf(v1c.x, w2.x, m);         m = fmaf(v1c.y, w2.y, m);
            m = fmaf(v1c.z, w2.z, m);         m = fmaf(v1c.w, w2.w, m);
            m = fmaf(v1d.x, w3.x, m);         m = fmaf(v1d.y, w3.y, m);
            m = fmaf(v1d.z, w3.z, m);         m = fmaf(v1d.w, w3.w, m);

            float s = (v1a.x + v1a.y) + (v1a.z + v1a.w);
            s += (v1b.x + v1b.y) + (v1b.z + v1b.w);
            s += (v1c.x + v1c.y) + (v1c.z + v1c.w);
            s += (v1d.x + v1d.y) + (v1d.z + v1d.w);

            float q = v1a.x * v1a.x;          q = fmaf(v1a.y, v1a.y, q);
            q = fmaf(v1a.z, v1a.z, q);        q = fmaf(v1a.w, v1a.w, q);
            q = fmaf(v1b.x, v1b.x, q);        q = fmaf(v1b.y, v1b.y, q);
            q = fmaf(v1b.z, v1b.z, q);        q = fmaf(v1b.w, v1b.w, q);
            q = fmaf(v1c.x, v1c.x, q);        q = fmaf(v1c.y, v1c.y, q);
            q = fmaf(v1c.z, v1c.z, q);        q = fmaf(v1c.w, v1c.w, q);
            q = fmaf(v1d.x, v1d.x, q);        q = fmaf(v1d.y, v1d.y, q);
            q = fmaf(v1d.z, v1d.z, q);        q = fmaf(v1d.w, v1d.w, q);

            m += __shfl_xor_sync(0xffffffffu, m, 1);
            s += __shfl_xor_sync(0xffffffffu, s, 1);
            q += __shfl_xor_sync(0xffffffffu, q, 1);
            m += __shfl_xor_sync(0xffffffffu, m, 2);
            s += __shfl_xor_sync(0xffffffffu, s, 2);
            q += __shfl_xor_sync(0xffffffffu, q, 2);

            if (qq == 0)
                acc += row_epilogue(m, s, q, lab1, lb, stab);
        }
    }

    // block reduction
    #pragma unroll
    for (int o = 16; o > 0; o >>= 1)
        acc += __shfl_xor_sync(0xffffffffu, acc, o);
    if ((tid & 31) == 0)
        warp_acc[tid >> 5] = acc;
    __syncthreads();
    if (tid == 0) {
        float t = 0.f;
        #pragma unroll
        for (int i = 0; i < THREADS / 32; i++) t += warp_acc[i];
        g_part[bid] = t;
        __threadfence();
        unsigned int old = atomicAdd(&g_count, 1u);
        s_last = (old == GRID - 1);
    }
    __syncthreads();

    // last block finalizes: fixed-order double reduction (deterministic)
    if (s_last && tid < 32) {
        double t = 0.0;
        for (int i = tid; i < GRID; i += 32)
            t += (double)g_part[i];
        #pragma unroll
        for (int o = 16; o > 0; o >>= 1)
            t += __shfl_xor_sync(0xffffffffu, t, o);
        if (tid == 0) {
            out[0] = (float)(t / (double)B_ROWS);
            g_count = 0;   // rearm for next graph replay
        }
    }
}

extern "C" void kernel_launch(void* const* d_in, const int* in_sizes, int n_in,
                              void* d_out, int out_size)
{
    const float* x        = (const float*)d_in[0];
    const int*   labels   = (const int*)d_in[1];
    const float* lin_w    = (const float*)d_in[2];
    const float* lin_b    = (const float*)d_in[3];
    const float* linear_p = (const float*)d_in[4];
    const float* bias_p   = (const float*)d_in[5];
    const float* centers  = (const float*)d_in[6];

    mcl_main<<<GRID, THREADS>>>(x, labels, lin_w, lin_b,
                                linear_p, bias_p, centers, (float*)d_out);
}